// round 6
// baseline (speedup 1.0000x reference)
#include <cuda_runtime.h>
#include <cuda_bf16.h>

#define MAX_PART 16384
__device__ float g_slice_sum[MAX_PART];   // per (row, slice) weighted sums
__device__ int   g_done_ctr = 0;

// ---------------------------------------------------------------------------
// Two warps per row, interleaved by 32-chunk group. Each warp keeps 8
// independent float4 loads in flight (launch_bounds gives 128 regs so ptxas
// can hold all destinations live -> real MLP ~ 8, vs ~2 at 44 regs before).
//   loss = (1/B) * sum_row (1/L) * sum_{t<L} (pred - log(align))^2
// Slice sums are statically owned -> deterministic; last CTA reduces in
// fixed order.
// ---------------------------------------------------------------------------
template <int BLOCK>
__global__ void __launch_bounds__(BLOCK, 2)
dploss_slice_kernel(const float* __restrict__ pred,
                    const float* __restrict__ align,
                    const int* __restrict__ lens,
                    float* __restrict__ out,
                    int C,        // float4 chunks per row (T/4)
                    int B,
                    int nWarpsTot) {
    const int lane = threadIdx.x & 31;
    const int warpId = (blockIdx.x * BLOCK + threadIdx.x) >> 5;
    const int warpStride = (gridDim.x * BLOCK) >> 5;

    for (int w = warpId; w < nWarpsTot; w += warpStride) {
        const int row = w >> 1;
        const int sl  = w & 1;                    // slice: even/odd 32-chunk groups
        const int L = __ldg(lens + row);
        const int nfull = L >> 2;
        const size_t base = (size_t)row * (size_t)C;
        const float4* __restrict__ p4 = reinterpret_cast<const float4*>(pred) + base;
        const float4* __restrict__ a4 = reinterpret_cast<const float4*>(align) + base;

        float s0 = 0.0f, s1 = 0.0f, s2 = 0.0f, s3 = 0.0f;

        int c = lane + (sl << 5);                 // first chunk of my slice
        // Hot loop: 4 groups of my slice per iteration (chunks c, c+64, c+128,
        // c+192), 8 independent LDG.128 all live at once.
        for (; c + 192 < nfull; c += 256) {
            float4 pA = p4[c];
            float4 aA = a4[c];
            float4 pB = p4[c + 64];
            float4 aB = a4[c + 64];
            float4 pC = p4[c + 128];
            float4 aC = a4[c + 128];
            float4 pD = p4[c + 192];
            float4 aD = a4[c + 192];

            float d;
            d = pA.x - __logf(aA.x); s0 = fmaf(d, d, s0);
            d = pA.y - __logf(aA.y); s0 = fmaf(d, d, s0);
            d = pA.z - __logf(aA.z); s0 = fmaf(d, d, s0);
            d = pA.w - __logf(aA.w); s0 = fmaf(d, d, s0);
            d = pB.x - __logf(aB.x); s1 = fmaf(d, d, s1);
            d = pB.y - __logf(aB.y); s1 = fmaf(d, d, s1);
            d = pB.z - __logf(aB.z); s1 = fmaf(d, d, s1);
            d = pB.w - __logf(aB.w); s1 = fmaf(d, d, s1);
            d = pC.x - __logf(aC.x); s2 = fmaf(d, d, s2);
            d = pC.y - __logf(aC.y); s2 = fmaf(d, d, s2);
            d = pC.z - __logf(aC.z); s2 = fmaf(d, d, s2);
            d = pC.w - __logf(aC.w); s2 = fmaf(d, d, s2);
            d = pD.x - __logf(aD.x); s3 = fmaf(d, d, s3);
            d = pD.y - __logf(aD.y); s3 = fmaf(d, d, s3);
            d = pD.z - __logf(aD.z); s3 = fmaf(d, d, s3);
            d = pD.w - __logf(aD.w); s3 = fmaf(d, d, s3);
        }
        // Remaining full groups of my slice.
        for (; c < nfull; c += 64) {
            float4 p = p4[c];
            float4 a = a4[c];
            float d;
            d = p.x - __logf(a.x); s0 = fmaf(d, d, s0);
            d = p.y - __logf(a.y); s1 = fmaf(d, d, s1);
            d = p.z - __logf(a.z); s2 = fmaf(d, d, s2);
            d = p.w - __logf(a.w); s3 = fmaf(d, d, s3);
        }
        // Partial tail chunk (1..3 valid elems): handled by the slice that
        // owns group (nfull>>5), by the lane matching (nfull&31).
        // Safe read: L&3 != 0 implies L < T, so chunk nfull < C.
        if ((L & 3) && (((nfull >> 5) & 1) == sl) && lane == (nfull & 31)) {
            float4 p = p4[nfull];
            float4 a = a4[nfull];
            int rem = L & 3;
            float d;
            d = p.x - __logf(a.x); s0 = fmaf(d, d, s0);
            if (rem > 1) { d = p.y - __logf(a.y); s1 = fmaf(d, d, s1); }
            if (rem > 2) { d = p.z - __logf(a.z); s2 = fmaf(d, d, s2); }
        }

        float s = (s0 + s1) + (s2 + s3);
        #pragma unroll
        for (int off = 16; off > 0; off >>= 1)
            s += __shfl_down_sync(0xFFFFFFFFu, s, off);
        if (lane == 0)
            g_slice_sum[w] = s * __frcp_rn((float)L);   // weight applied per slice
    }

    // Completion signal; last CTA reduces all slice sums in fixed order.
    __syncthreads();
    __shared__ bool s_is_last;
    if (threadIdx.x == 0) {
        __threadfence();
        int old = atomicAdd(&g_done_ctr, 1);
        s_is_last = (old == (int)gridDim.x - 1);
    }
    __syncthreads();

    if (s_is_last) {
        float v = 0.0f;
        for (int i = threadIdx.x; i < nWarpsTot; i += BLOCK)
            v += g_slice_sum[i];
        __shared__ float warp_sums[BLOCK / 32];
        #pragma unroll
        for (int off = 16; off > 0; off >>= 1)
            v += __shfl_down_sync(0xFFFFFFFFu, v, off);
        if ((threadIdx.x & 31) == 0)
            warp_sums[threadIdx.x >> 5] = v;
        __syncthreads();
        if (threadIdx.x == 0) {
            float t = 0.0f;
            #pragma unroll
            for (int wv = 0; wv < BLOCK / 32; wv++)
                t += warp_sums[wv];
            out[0] = t / (float)B;
            g_done_ctr = 0;   // reset for next graph replay
        }
    }
}

extern "C" void kernel_launch(void* const* d_in, const int* in_sizes, int n_in,
                              void* d_out, int out_size) {
    const float* pred  = (const float*)d_in[0];
    const float* align = (const float*)d_in[1];
    const int*   lens  = (const int*)d_in[2];
    float* out = (float*)d_out;

    const int B = in_sizes[2];
    const int T = in_sizes[0] / B;
    const int C = T >> 2;
    const int nWarpsTot = B * 2;                 // 2 slices per row

    constexpr int BLOCK = 256;                   // 8 warps per CTA
    int grid = (nWarpsTot + (BLOCK / 32) - 1) / (BLOCK / 32);
    if (grid < 1) grid = 1;
    if (grid > 8192) grid = 8192;

    dploss_slice_kernel<BLOCK><<<grid, BLOCK>>>(pred, align, lens, out,
                                                C, B, nWarpsTot);
}